// round 15
// baseline (speedup 1.0000x reference)
#include <cuda_runtime.h>
#include <cuda_bf16.h>
#include <math.h>
#include <stdint.h>

#define NN 100000
#define NE 1600000
#define DH 128
#define NC 64
#define SBLK 1024
#define NSB ((NN + SBLK - 1) / SBLK)   // 98

// ---- persistent scratch (no allocations allowed) ----
__device__ int   g_deg[NN];
__device__ float g_inv[NN];
__device__ int   g_rp[NN + 1];
__device__ int   g_cur[NN];
__device__ int   g_col[NE];
__device__ int   g_bsum[NSB];
__device__ float g_h1[(size_t)NN * DH];
__device__ float g_h2[(size_t)NN * DH];
__device__ __nv_bfloat16 g_featb[(size_t)NN * DH];
__device__ __nv_bfloat16 g_h1b[(size_t)NN * DH];

// ---------------- tf32 warp-MMA helpers ----------------
__device__ __forceinline__ uint32_t tf32_of(float f) {
    uint32_t r;
    asm("cvt.rna.tf32.f32 %0, %1;" : "=r"(r) : "f"(f));
    return r;
}
__device__ __forceinline__ void mma_tf32(float (&c)[4], const uint32_t (&a)[4],
                                         const uint32_t (&b)[2]) {
    asm volatile(
        "mma.sync.aligned.m16n8k8.row.col.f32.tf32.tf32.f32 "
        "{%0,%1,%2,%3}, {%4,%5,%6,%7}, {%8,%9}, {%0,%1,%2,%3};"
        : "+f"(c[0]), "+f"(c[1]), "+f"(c[2]), "+f"(c[3])
        : "r"(a[0]), "r"(a[1]), "r"(a[2]), "r"(a[3]), "r"(b[0]), "r"(b[1]));
}

// ---------------- init: zero deg + fp32->bf16 feat conversion (fused) ----------------
__global__ void k_init(const float4* __restrict__ x, __nv_bfloat162* __restrict__ y) {
    int i = blockIdx.x * blockDim.x + threadIdx.x;
    if (i < NN) g_deg[i] = 0;
    if (i < NN * DH / 4) {
        float4 v = x[i];
        y[2 * i]     = __floats2bfloat162_rn(v.x, v.y);
        y[2 * i + 1] = __floats2bfloat162_rn(v.z, v.w);
    }
}

__global__ void k_count(const int* __restrict__ dst) {
    int e = blockIdx.x * blockDim.x + threadIdx.x;
    if (e < NE) atomicAdd(&g_deg[dst[e]], 1);
}

// phase A: per-block chunk sums
__global__ void k_scanA() {
    __shared__ int wsum[32];
    int tid = threadIdx.x, lane = tid & 31, wid = tid >> 5;
    int i = blockIdx.x * SBLK + tid;
    int v = (i < NN) ? g_deg[i] : 0;
    int x = v;
#pragma unroll
    for (int o = 16; o > 0; o >>= 1) x += __shfl_xor_sync(0xffffffffu, x, o);
    if (lane == 0) wsum[wid] = x;
    __syncthreads();
    if (wid == 0) {
        int y = (lane < SBLK / 32) ? wsum[lane] : 0;
#pragma unroll
        for (int o = 16; o > 0; o >>= 1) y += __shfl_xor_sync(0xffffffffu, y, o);
        if (lane == 0) g_bsum[blockIdx.x] = y;
    }
}

// phase B: single small block scans NSB block sums (exclusive), writes total
__global__ void k_scanB() {
    __shared__ int s[NSB];
    int tid = threadIdx.x;           // 128 threads
    if (tid < NSB) s[tid] = g_bsum[tid];
    __syncthreads();
    if (tid == 0) {
        int acc = 0;
        for (int b = 0; b < NSB; b++) { int t = s[b]; s[b] = acc; acc += t; }
        g_rp[NN] = acc;
    }
    __syncthreads();
    if (tid < NSB) g_bsum[tid] = s[tid];
}

// phase C: per-block exclusive scan + offset, write rp/inv, reset cur
__global__ void k_scanC() {
    __shared__ int wsum[32];
    int tid = threadIdx.x, lane = tid & 31, wid = tid >> 5;
    int i = blockIdx.x * SBLK + tid;
    int v = (i < NN) ? g_deg[i] : 0;
    int x = v;
#pragma unroll
    for (int o = 1; o < 32; o <<= 1) {
        int y = __shfl_up_sync(0xffffffffu, x, o);
        if (lane >= o) x += y;
    }
    if (lane == 31) wsum[wid] = x;
    __syncthreads();
    if (wid == 0) {
        int y = (lane < SBLK / 32) ? wsum[lane] : 0;
        int z = y;
#pragma unroll
        for (int o = 1; o < 32; o <<= 1) {
            int t = __shfl_up_sync(0xffffffffu, z, o);
            if (lane >= o) z += t;
        }
        if (lane < SBLK / 32) wsum[lane] = z - y;   // exclusive warp offsets
    }
    __syncthreads();
    if (i < NN) {
        g_rp[i]  = g_bsum[blockIdx.x] + wsum[wid] + x - v;
        g_inv[i] = 1.0f / (float)(v > 1 ? v : 1);
        g_cur[i] = 0;
    }
}

__global__ void k_fill(const int* __restrict__ src, const int* __restrict__ dst) {
    int e = blockIdx.x * blockDim.x + threadIdx.x;
    if (e < NE) {
        int d = dst[e];
        int p = atomicAdd(&g_cur[d], 1);
        g_col[g_rp[d] + p] = src[e];
    }
}

// ---------------- fused mean-agg + GEMM: Y = relu(mean_agg(xb) @ W^T + b) ----------------
// block 256 thr (8 warps), tile M=64, N=128, K=128
// phase 1: each warp aggregates 8 nodes (bf16 gather, fp32 acc) into As
// phase 2: tf32 warp-MMA as before
__global__ void k_agg_gemm(const __nv_bfloat16* __restrict__ xb, const float* __restrict__ W,
                           const float* __restrict__ bias, float* __restrict__ Y,
                           __nv_bfloat16* __restrict__ Yb) {
    extern __shared__ float sm[];
    float* As = sm;               // [64][132]
    float* Bs = sm + 64 * 132;    // [128][132]
    int tid = threadIdx.x;
    int row0 = blockIdx.x * 64;
    int warp = tid >> 5, lane = tid & 31;

    const float4* W4 = (const float4*)W;
    for (int idx = tid; idx < 128 * 32; idx += 256) {
        int n = idx >> 5, kq = idx & 31;
        *(float4*)&Bs[n * 132 + kq * 4] = W4[idx];
    }

    // phase 1: aggregate 8 nodes per warp directly into As
    const uint2* xv = (const uint2*)xb;   // bf16 row = 32 uint2
    for (int t = 0; t < 8; t++) {
        int r = warp * 8 + t;
        int node = row0 + r;
        float4 acc = make_float4(0.f, 0.f, 0.f, 0.f);
        if (node < NN) {
            int s = g_rp[node], e = g_rp[node + 1];
            int j = s;
            for (; j + 4 <= e; j += 4) {
                int n0 = g_col[j], n1 = g_col[j + 1], n2 = g_col[j + 2], n3 = g_col[j + 3];
                uint2 u0 = xv[n0 * 32 + lane];
                uint2 u1 = xv[n1 * 32 + lane];
                uint2 u2 = xv[n2 * 32 + lane];
                uint2 u3 = xv[n3 * 32 + lane];
#pragma unroll
                for (int q = 0; q < 4; q++) {
                    uint2 u = q == 0 ? u0 : q == 1 ? u1 : q == 2 ? u2 : u3;
                    float2 lo = __bfloat1622float2(*(__nv_bfloat162*)&u.x);
                    float2 hi = __bfloat1622float2(*(__nv_bfloat162*)&u.y);
                    acc.x += lo.x; acc.y += lo.y; acc.z += hi.x; acc.w += hi.y;
                }
            }
            for (; j < e; j++) {
                uint2 u = xv[g_col[j] * 32 + lane];
                float2 lo = __bfloat1622float2(*(__nv_bfloat162*)&u.x);
                float2 hi = __bfloat1622float2(*(__nv_bfloat162*)&u.y);
                acc.x += lo.x; acc.y += lo.y; acc.z += hi.x; acc.w += hi.y;
            }
            float id = g_inv[node];
            acc.x *= id; acc.y *= id; acc.z *= id; acc.w *= id;
        }
        *(float4*)&As[r * 132 + lane * 4] = acc;
    }
    __syncthreads();

    // phase 2: MMA
    int warpM = warp & 1;
    int warpN = warp >> 1;
    int g = lane >> 2, tg = lane & 3;

    float acc[2][4][4];
#pragma unroll
    for (int t = 0; t < 2; t++)
#pragma unroll
        for (int j = 0; j < 4; j++)
#pragma unroll
            for (int q = 0; q < 4; q++) acc[t][j][q] = 0.f;

#pragma unroll
    for (int k0 = 0; k0 < 128; k0 += 8) {
        uint32_t a[2][4], b[4][2];
#pragma unroll
        for (int t = 0; t < 2; t++) {
            int r = warpM * 32 + t * 16 + g;
            a[t][0] = tf32_of(As[r * 132 + k0 + tg]);
            a[t][1] = tf32_of(As[(r + 8) * 132 + k0 + tg]);
            a[t][2] = tf32_of(As[r * 132 + k0 + tg + 4]);
            a[t][3] = tf32_of(As[(r + 8) * 132 + k0 + tg + 4]);
        }
#pragma unroll
        for (int j = 0; j < 4; j++) {
            int n = warpN * 32 + j * 8 + g;
            b[j][0] = tf32_of(Bs[n * 132 + k0 + tg]);
            b[j][1] = tf32_of(Bs[n * 132 + k0 + tg + 4]);
        }
#pragma unroll
        for (int t = 0; t < 2; t++)
#pragma unroll
            for (int j = 0; j < 4; j++) mma_tf32(acc[t][j], a[t], b[j]);
    }

#pragma unroll
    for (int t = 0; t < 2; t++) {
        int r = row0 + warpM * 32 + t * 16 + g;
#pragma unroll
        for (int j = 0; j < 4; j++) {
            int c = warpN * 32 + j * 8 + tg * 2;
            float bc0 = bias[c], bc1 = bias[c + 1];
            if (r < NN) {
                float2 o;
                o.x = fmaxf(acc[t][j][0] + bc0, 0.f);
                o.y = fmaxf(acc[t][j][1] + bc1, 0.f);
                *(float2*)&Y[(size_t)r * 128 + c] = o;
                if (Yb) *(__nv_bfloat162*)&Yb[(size_t)r * 128 + c] = __floats2bfloat162_rn(o.x, o.y);
            }
            if (r + 8 < NN) {
                float2 o;
                o.x = fmaxf(acc[t][j][2] + bc0, 0.f);
                o.y = fmaxf(acc[t][j][3] + bc1, 0.f);
                *(float2*)&Y[(size_t)(r + 8) * 128 + c] = o;
                if (Yb) *(__nv_bfloat162*)&Yb[(size_t)(r + 8) * 128 + c] = __floats2bfloat162_rn(o.x, o.y);
            }
        }
    }
}

// ---------------- logits + log_softmax via tf32 warp-MMA ----------------
__global__ void k_logits(const float* __restrict__ Wl, const float* __restrict__ bl,
                         float* __restrict__ out) {
    extern __shared__ float sm[];
    float* As = sm;               // [128][132]
    float* Ws = sm + 128 * 132;   // [64][132]
    int tid = threadIdx.x;
    int row0 = blockIdx.x * 128;
    int warp = tid >> 5, lane = tid & 31;
    int warpM = warp & 3;
    int warpN = warp >> 2;
    int g = lane >> 2, tg = lane & 3;

    float acc[2][4][4];
#pragma unroll
    for (int t = 0; t < 2; t++)
#pragma unroll
        for (int j = 0; j < 4; j++)
#pragma unroll
            for (int q = 0; q < 4; q++) acc[t][j][q] = 0.f;

    const float4* Wl4 = (const float4*)Wl;
    for (int ph = 0; ph < 2; ph++) {
        const float* X = ph ? g_h2 : g_h1;
        const float4* X4 = (const float4*)X;
        __syncthreads();
        for (int idx = tid; idx < 128 * 32; idx += 256) {
            int r = idx >> 5, kq = idx & 31;
            int gr = row0 + r;
            float4 v = (gr < NN) ? X4[(size_t)gr * 32 + kq] : make_float4(0.f, 0.f, 0.f, 0.f);
            *(float4*)&As[r * 132 + kq * 4] = v;
        }
        for (int idx = tid; idx < 64 * 32; idx += 256) {
            int n = idx >> 5, kq = idx & 31;
            float4 v = Wl4[n * 64 + ph * 32 + kq];
            *(float4*)&Ws[n * 132 + kq * 4] = v;
        }
        __syncthreads();

#pragma unroll
        for (int k0 = 0; k0 < 128; k0 += 8) {
            uint32_t a[2][4], b[4][2];
#pragma unroll
            for (int t = 0; t < 2; t++) {
                int r = warpM * 32 + t * 16 + g;
                a[t][0] = tf32_of(As[r * 132 + k0 + tg]);
                a[t][1] = tf32_of(As[(r + 8) * 132 + k0 + tg]);
                a[t][2] = tf32_of(As[r * 132 + k0 + tg + 4]);
                a[t][3] = tf32_of(As[(r + 8) * 132 + k0 + tg + 4]);
            }
#pragma unroll
            for (int j = 0; j < 4; j++) {
                int n = warpN * 32 + j * 8 + g;
                b[j][0] = tf32_of(Ws[n * 132 + k0 + tg]);
                b[j][1] = tf32_of(Ws[n * 132 + k0 + tg + 4]);
            }
#pragma unroll
            for (int t = 0; t < 2; t++)
#pragma unroll
                for (int j = 0; j < 4; j++) mma_tf32(acc[t][j], a[t], b[j]);
        }
    }

    __syncthreads();
    float* Ls = sm;
#pragma unroll
    for (int t = 0; t < 2; t++) {
        int r = warpM * 32 + t * 16 + g;
#pragma unroll
        for (int j = 0; j < 4; j++) {
            int c = warpN * 32 + j * 8 + tg * 2;
            float bc0 = bl[c], bc1 = bl[c + 1];
            Ls[r * 68 + c]           = acc[t][j][0] + bc0;
            Ls[r * 68 + c + 1]       = acc[t][j][1] + bc1;
            Ls[(r + 8) * 68 + c]     = acc[t][j][2] + bc0;
            Ls[(r + 8) * 68 + c + 1] = acc[t][j][3] + bc1;
        }
    }
    __syncthreads();

    for (int rr = warp * 16; rr < warp * 16 + 16; rr++) {
        float v0 = Ls[rr * 68 + lane];
        float v1 = Ls[rr * 68 + 32 + lane];
        float m = fmaxf(v0, v1);
#pragma unroll
        for (int o = 16; o > 0; o >>= 1) m = fmaxf(m, __shfl_xor_sync(0xffffffffu, m, o));
        float s = expf(v0 - m) + expf(v1 - m);
#pragma unroll
        for (int o = 16; o > 0; o >>= 1) s += __shfl_xor_sync(0xffffffffu, s, o);
        float lse = m + logf(s);
        int gr = row0 + rr;
        if (gr < NN) {
            out[(size_t)gr * 64 + lane]      = v0 - lse;
            out[(size_t)gr * 64 + 32 + lane] = v1 - lse;
        }
    }
}

extern "C" void kernel_launch(void* const* d_in, const int* in_sizes, int n_in,
                              void* d_out, int out_size) {
    const float* feat = (const float*)d_in[0];
    const int*   src  = (const int*)d_in[1];
    const int*   dst  = (const int*)d_in[2];
    const float* W1   = (const float*)d_in[3];
    const float* b1   = (const float*)d_in[4];
    const float* W2   = (const float*)d_in[5];
    const float* b2   = (const float*)d_in[6];
    const float* Wl   = (const float*)d_in[7];
    const float* bl   = (const float*)d_in[8];
    float* out = (float*)d_out;

    void *p_h1, *p_h2, *p_fb, *p_h1b;
    cudaGetSymbolAddress(&p_h1,  g_h1);
    cudaGetSymbolAddress(&p_h2,  g_h2);
    cudaGetSymbolAddress(&p_fb,  g_featb);
    cudaGetSymbolAddress(&p_h1b, g_h1b);

    const int SMEM_GEMM   = (64 * 132 + 128 * 132) * 4;   // 101376
    const int SMEM_LOGITS = (128 * 132 + 64 * 132) * 4;   // 101376
    cudaFuncSetAttribute(k_agg_gemm, cudaFuncAttributeMaxDynamicSharedMemorySize, SMEM_GEMM);
    cudaFuncSetAttribute(k_logits,   cudaFuncAttributeMaxDynamicSharedMemorySize, SMEM_LOGITS);

    // graph build + feat conversion
    k_init <<<(NN * DH / 4 + 255) / 256, 256>>>((const float4*)feat, (__nv_bfloat162*)p_fb);
    k_count<<<(NE + 255) / 256, 256>>>(dst);
    k_scanA<<<NSB, SBLK>>>();
    k_scanB<<<1, 128>>>();
    k_scanC<<<NSB, SBLK>>>();
    k_fill <<<(NE + 255) / 256, 256>>>(src, dst);

    // layer 1 (fused agg+gemm)
    k_agg_gemm<<<(NN + 63) / 64, 256, SMEM_GEMM>>>((const __nv_bfloat16*)p_fb, W1, b1,
                                                   (float*)p_h1, (__nv_bfloat16*)p_h1b);

    // layer 2 (fused agg+gemm)
    k_agg_gemm<<<(NN + 63) / 64, 256, SMEM_GEMM>>>((const __nv_bfloat16*)p_h1b, W2, b2,
                                                   (float*)p_h2, (__nv_bfloat16*)0);

    // logits + log_softmax
    k_logits<<<(NN + 127) / 128, 256, SMEM_LOGITS>>>(Wl, bl, out);
}

// round 16
// speedup vs baseline: 1.3073x; 1.3073x over previous
#include <cuda_runtime.h>
#include <cuda_bf16.h>
#include <math.h>
#include <stdint.h>

#define NN 100000
#define NE 1600000
#define DH 128
#define NC 64
#define SBLK 1024
#define NSB ((NN + SBLK - 1) / SBLK)   // 98

// ---- persistent scratch (no allocations allowed) ----
__device__ int   g_deg[NN];
__device__ float g_inv[NN];
__device__ int   g_rp[NN + 1];
__device__ int   g_cur[NN];
__device__ int   g_col[NE];
__device__ int   g_bsum[NSB];
__device__ float g_agg[(size_t)NN * DH];
__device__ float g_h1[(size_t)NN * DH];
__device__ float g_h2[(size_t)NN * DH];
__device__ __nv_bfloat16 g_featb[(size_t)NN * DH];
__device__ __nv_bfloat16 g_h1b[(size_t)NN * DH];

// ---------------- tf32 warp-MMA helpers ----------------
__device__ __forceinline__ uint32_t tf32_of(float f) {
    uint32_t r;
    asm("cvt.rna.tf32.f32 %0, %1;" : "=r"(r) : "f"(f));
    return r;
}
__device__ __forceinline__ void mma_tf32(float (&c)[4], const uint32_t (&a)[4],
                                         const uint32_t (&b)[2]) {
    asm volatile(
        "mma.sync.aligned.m16n8k8.row.col.f32.tf32.tf32.f32 "
        "{%0,%1,%2,%3}, {%4,%5,%6,%7}, {%8,%9}, {%0,%1,%2,%3};"
        : "+f"(c[0]), "+f"(c[1]), "+f"(c[2]), "+f"(c[3])
        : "r"(a[0]), "r"(a[1]), "r"(a[2]), "r"(a[3]), "r"(b[0]), "r"(b[1]));
}

// ---------------- init: zero deg + fp32->bf16 feat conversion (fused) ----------------
__global__ void k_init(const float4* __restrict__ x, __nv_bfloat162* __restrict__ y) {
    int i = blockIdx.x * blockDim.x + threadIdx.x;
    if (i < NN) g_deg[i] = 0;
    if (i < NN * DH / 4) {
        float4 v = x[i];
        y[2 * i]     = __floats2bfloat162_rn(v.x, v.y);
        y[2 * i + 1] = __floats2bfloat162_rn(v.z, v.w);
    }
}

__global__ void k_count(const int* __restrict__ dst) {
    int e = blockIdx.x * blockDim.x + threadIdx.x;
    if (e < NE) atomicAdd(&g_deg[dst[e]], 1);
}

// phase A: per-block chunk sums
__global__ void k_scanA() {
    __shared__ int wsum[32];
    int tid = threadIdx.x, lane = tid & 31, wid = tid >> 5;
    int i = blockIdx.x * SBLK + tid;
    int v = (i < NN) ? g_deg[i] : 0;
    int x = v;
#pragma unroll
    for (int o = 16; o > 0; o >>= 1) x += __shfl_xor_sync(0xffffffffu, x, o);
    if (lane == 0) wsum[wid] = x;
    __syncthreads();
    if (wid == 0) {
        int y = (lane < SBLK / 32) ? wsum[lane] : 0;
#pragma unroll
        for (int o = 16; o > 0; o >>= 1) y += __shfl_xor_sync(0xffffffffu, y, o);
        if (lane == 0) g_bsum[blockIdx.x] = y;
    }
}

// phase B: single small block scans NSB block sums (exclusive), writes total
__global__ void k_scanB() {
    __shared__ int s[NSB];
    int tid = threadIdx.x;           // 128 threads
    if (tid < NSB) s[tid] = g_bsum[tid];
    __syncthreads();
    if (tid == 0) {
        int acc = 0;
        for (int b = 0; b < NSB; b++) { int t = s[b]; s[b] = acc; acc += t; }
        g_rp[NN] = acc;
    }
    __syncthreads();
    if (tid < NSB) g_bsum[tid] = s[tid];
}

// phase C: per-block exclusive scan + offset, write rp/inv, reset cur
__global__ void k_scanC() {
    __shared__ int wsum[32];
    int tid = threadIdx.x, lane = tid & 31, wid = tid >> 5;
    int i = blockIdx.x * SBLK + tid;
    int v = (i < NN) ? g_deg[i] : 0;
    int x = v;
#pragma unroll
    for (int o = 1; o < 32; o <<= 1) {
        int y = __shfl_up_sync(0xffffffffu, x, o);
        if (lane >= o) x += y;
    }
    if (lane == 31) wsum[wid] = x;
    __syncthreads();
    if (wid == 0) {
        int y = (lane < SBLK / 32) ? wsum[lane] : 0;
        int z = y;
#pragma unroll
        for (int o = 1; o < 32; o <<= 1) {
            int t = __shfl_up_sync(0xffffffffu, z, o);
            if (lane >= o) z += t;
        }
        if (lane < SBLK / 32) wsum[lane] = z - y;   // exclusive warp offsets
    }
    __syncthreads();
    if (i < NN) {
        g_rp[i]  = g_bsum[blockIdx.x] + wsum[wid] + x - v;
        g_inv[i] = 1.0f / (float)(v > 1 ? v : 1);
        g_cur[i] = 0;
    }
}

__global__ void k_fill(const int* __restrict__ src, const int* __restrict__ dst) {
    int e = blockIdx.x * blockDim.x + threadIdx.x;
    if (e < NE) {
        int d = dst[e];
        int p = atomicAdd(&g_cur[d], 1);
        g_col[g_rp[d] + p] = src[e];
    }
}

// ---------------- mean aggregation from bf16: one warp per node (high occupancy) ----------------
__global__ void k_agg_bf(const __nv_bfloat16* __restrict__ xb, float* __restrict__ out) {
    int gw = (blockIdx.x * blockDim.x + threadIdx.x) >> 5;
    if (gw >= NN) return;
    int lane = threadIdx.x & 31;
    int s = g_rp[gw], e = g_rp[gw + 1];
    const uint2* xv = (const uint2*)xb;   // row = 32 uint2
    float4 acc = make_float4(0.f, 0.f, 0.f, 0.f);
    int j = s;
    for (; j + 4 <= e; j += 4) {
        int n0 = g_col[j], n1 = g_col[j + 1], n2 = g_col[j + 2], n3 = g_col[j + 3];
        uint2 u0 = xv[n0 * 32 + lane];
        uint2 u1 = xv[n1 * 32 + lane];
        uint2 u2 = xv[n2 * 32 + lane];
        uint2 u3 = xv[n3 * 32 + lane];
#pragma unroll
        for (int q = 0; q < 4; q++) {
            uint2 u = q == 0 ? u0 : q == 1 ? u1 : q == 2 ? u2 : u3;
            float2 lo = __bfloat1622float2(*(__nv_bfloat162*)&u.x);
            float2 hi = __bfloat1622float2(*(__nv_bfloat162*)&u.y);
            acc.x += lo.x; acc.y += lo.y; acc.z += hi.x; acc.w += hi.y;
        }
    }
    for (; j < e; j++) {
        uint2 u = xv[g_col[j] * 32 + lane];
        float2 lo = __bfloat1622float2(*(__nv_bfloat162*)&u.x);
        float2 hi = __bfloat1622float2(*(__nv_bfloat162*)&u.y);
        acc.x += lo.x; acc.y += lo.y; acc.z += hi.x; acc.w += hi.y;
    }
    float id = g_inv[gw];
    acc.x *= id; acc.y *= id; acc.z *= id; acc.w *= id;
    ((float4*)out)[gw * 32 + lane] = acc;
}

// ---------------- Y[M,128] = relu(A[M,128] @ W^T + b) via tf32 warp-MMA ----------------
__global__ void k_gemm128(const float* __restrict__ A, const float* __restrict__ W,
                          const float* __restrict__ bias, float* __restrict__ Y,
                          __nv_bfloat16* __restrict__ Yb) {
    extern __shared__ float sm[];
    float* As = sm;               // [64][132]
    float* Bs = sm + 64 * 132;    // [128][132]
    int tid = threadIdx.x;
    int row0 = blockIdx.x * 64;

    const float4* W4 = (const float4*)W;
    for (int idx = tid; idx < 128 * 32; idx += 256) {
        int n = idx >> 5, kq = idx & 31;
        *(float4*)&Bs[n * 132 + kq * 4] = W4[idx];
    }
    const float4* A4 = (const float4*)A;
    for (int idx = tid; idx < 64 * 32; idx += 256) {
        int r = idx >> 5, kq = idx & 31;
        int gr = row0 + r;
        float4 v = (gr < NN) ? A4[(size_t)gr * 32 + kq] : make_float4(0.f, 0.f, 0.f, 0.f);
        *(float4*)&As[r * 132 + kq * 4] = v;
    }
    __syncthreads();

    int warp = tid >> 5, lane = tid & 31;
    int warpM = warp & 1;
    int warpN = warp >> 1;
    int g = lane >> 2, tg = lane & 3;

    float acc[2][4][4];
#pragma unroll
    for (int t = 0; t < 2; t++)
#pragma unroll
        for (int j = 0; j < 4; j++)
#pragma unroll
            for (int q = 0; q < 4; q++) acc[t][j][q] = 0.f;

#pragma unroll
    for (int k0 = 0; k0 < 128; k0 += 8) {
        uint32_t a[2][4], b[4][2];
#pragma unroll
        for (int t = 0; t < 2; t++) {
            int r = warpM * 32 + t * 16 + g;
            a[t][0] = tf32_of(As[r * 132 + k0 + tg]);
            a[t][1] = tf32_of(As[(r + 8) * 132 + k0 + tg]);
            a[t][2] = tf32_of(As[r * 132 + k0 + tg + 4]);
            a[t][3] = tf32_of(As[(r + 8) * 132 + k0 + tg + 4]);
        }
#pragma unroll
        for (int j = 0; j < 4; j++) {
            int n = warpN * 32 + j * 8 + g;
            b[j][0] = tf32_of(Bs[n * 132 + k0 + tg]);
            b[j][1] = tf32_of(Bs[n * 132 + k0 + tg + 4]);
        }
#pragma unroll
        for (int t = 0; t < 2; t++)
#pragma unroll
            for (int j = 0; j < 4; j++) mma_tf32(acc[t][j], a[t], b[j]);
    }

#pragma unroll
    for (int t = 0; t < 2; t++) {
        int r = row0 + warpM * 32 + t * 16 + g;
#pragma unroll
        for (int j = 0; j < 4; j++) {
            int c = warpN * 32 + j * 8 + tg * 2;
            float bc0 = bias[c], bc1 = bias[c + 1];
            if (r < NN) {
                float2 o;
                o.x = fmaxf(acc[t][j][0] + bc0, 0.f);
                o.y = fmaxf(acc[t][j][1] + bc1, 0.f);
                *(float2*)&Y[(size_t)r * 128 + c] = o;
                if (Yb) *(__nv_bfloat162*)&Yb[(size_t)r * 128 + c] = __floats2bfloat162_rn(o.x, o.y);
            }
            if (r + 8 < NN) {
                float2 o;
                o.x = fmaxf(acc[t][j][2] + bc0, 0.f);
                o.y = fmaxf(acc[t][j][3] + bc1, 0.f);
                *(float2*)&Y[(size_t)(r + 8) * 128 + c] = o;
                if (Yb) *(__nv_bfloat162*)&Yb[(size_t)(r + 8) * 128 + c] = __floats2bfloat162_rn(o.x, o.y);
            }
        }
    }
}

// ---------------- logits + log_softmax via tf32 warp-MMA ----------------
__global__ void k_logits(const float* __restrict__ Wl, const float* __restrict__ bl,
                         float* __restrict__ out) {
    extern __shared__ float sm[];
    float* As = sm;               // [128][132]
    float* Ws = sm + 128 * 132;   // [64][132]
    int tid = threadIdx.x;
    int row0 = blockIdx.x * 128;
    int warp = tid >> 5, lane = tid & 31;
    int warpM = warp & 3;
    int warpN = warp >> 2;
    int g = lane >> 2, tg = lane & 3;

    float acc[2][4][4];
#pragma unroll
    for (int t = 0; t < 2; t++)
#pragma unroll
        for (int j = 0; j < 4; j++)
#pragma unroll
            for (int q = 0; q < 4; q++) acc[t][j][q] = 0.f;

    const float4* Wl4 = (const float4*)Wl;
    for (int ph = 0; ph < 2; ph++) {
        const float* X = ph ? g_h2 : g_h1;
        const float4* X4 = (const float4*)X;
        __syncthreads();
        for (int idx = tid; idx < 128 * 32; idx += 256) {
            int r = idx >> 5, kq = idx & 31;
            int gr = row0 + r;
            float4 v = (gr < NN) ? X4[(size_t)gr * 32 + kq] : make_float4(0.f, 0.f, 0.f, 0.f);
            *(float4*)&As[r * 132 + kq * 4] = v;
        }
        for (int idx = tid; idx < 64 * 32; idx += 256) {
            int n = idx >> 5, kq = idx & 31;
            float4 v = Wl4[n * 64 + ph * 32 + kq];
            *(float4*)&Ws[n * 132 + kq * 4] = v;
        }
        __syncthreads();

#pragma unroll
        for (int k0 = 0; k0 < 128; k0 += 8) {
            uint32_t a[2][4], b[4][2];
#pragma unroll
            for (int t = 0; t < 2; t++) {
                int r = warpM * 32 + t * 16 + g;
                a[t][0] = tf32_of(As[r * 132 + k0 + tg]);
                a[t][1] = tf32_of(As[(r + 8) * 132 + k0 + tg]);
                a[t][2] = tf32_of(As[r * 132 + k0 + tg + 4]);
                a[t][3] = tf32_of(As[(r + 8) * 132 + k0 + tg + 4]);
            }
#pragma unroll
            for (int j = 0; j < 4; j++) {
                int n = warpN * 32 + j * 8 + g;
                b[j][0] = tf32_of(Ws[n * 132 + k0 + tg]);
                b[j][1] = tf32_of(Ws[n * 132 + k0 + tg + 4]);
            }
#pragma unroll
            for (int t = 0; t < 2; t++)
#pragma unroll
                for (int j = 0; j < 4; j++) mma_tf32(acc[t][j], a[t], b[j]);
        }
    }

    __syncthreads();
    float* Ls = sm;
#pragma unroll
    for (int t = 0; t < 2; t++) {
        int r = warpM * 32 + t * 16 + g;
#pragma unroll
        for (int j = 0; j < 4; j++) {
            int c = warpN * 32 + j * 8 + tg * 2;
            float bc0 = bl[c], bc1 = bl[c + 1];
            Ls[r * 68 + c]           = acc[t][j][0] + bc0;
            Ls[r * 68 + c + 1]       = acc[t][j][1] + bc1;
            Ls[(r + 8) * 68 + c]     = acc[t][j][2] + bc0;
            Ls[(r + 8) * 68 + c + 1] = acc[t][j][3] + bc1;
        }
    }
    __syncthreads();

    for (int rr = warp * 16; rr < warp * 16 + 16; rr++) {
        float v0 = Ls[rr * 68 + lane];
        float v1 = Ls[rr * 68 + 32 + lane];
        float m = fmaxf(v0, v1);
#pragma unroll
        for (int o = 16; o > 0; o >>= 1) m = fmaxf(m, __shfl_xor_sync(0xffffffffu, m, o));
        float s = expf(v0 - m) + expf(v1 - m);
#pragma unroll
        for (int o = 16; o > 0; o >>= 1) s += __shfl_xor_sync(0xffffffffu, s, o);
        float lse = m + logf(s);
        int gr = row0 + rr;
        if (gr < NN) {
            out[(size_t)gr * 64 + lane]      = v0 - lse;
            out[(size_t)gr * 64 + 32 + lane] = v1 - lse;
        }
    }
}

extern "C" void kernel_launch(void* const* d_in, const int* in_sizes, int n_in,
                              void* d_out, int out_size) {
    const float* feat = (const float*)d_in[0];
    const int*   src  = (const int*)d_in[1];
    const int*   dst  = (const int*)d_in[2];
    const float* W1   = (const float*)d_in[3];
    const float* b1   = (const float*)d_in[4];
    const float* W2   = (const float*)d_in[5];
    const float* b2   = (const float*)d_in[6];
    const float* Wl   = (const float*)d_in[7];
    const float* bl   = (const float*)d_in[8];
    float* out = (float*)d_out;

    void *p_agg, *p_h1, *p_h2, *p_fb, *p_h1b;
    cudaGetSymbolAddress(&p_agg, g_agg);
    cudaGetSymbolAddress(&p_h1,  g_h1);
    cudaGetSymbolAddress(&p_h2,  g_h2);
    cudaGetSymbolAddress(&p_fb,  g_featb);
    cudaGetSymbolAddress(&p_h1b, g_h1b);

    const int SMEM_GEMM   = (64 * 132 + 128 * 132) * 4;   // 101376
    const int SMEM_LOGITS = (128 * 132 + 64 * 132) * 4;   // 101376
    cudaFuncSetAttribute(k_gemm128, cudaFuncAttributeMaxDynamicSharedMemorySize, SMEM_GEMM);
    cudaFuncSetAttribute(k_logits,  cudaFuncAttributeMaxDynamicSharedMemorySize, SMEM_LOGITS);

    // graph build + feat conversion
    k_init <<<(NN * DH / 4 + 255) / 256, 256>>>((const float4*)feat, (__nv_bfloat162*)p_fb);
    k_count<<<(NE + 255) / 256, 256>>>(dst);
    k_scanA<<<NSB, SBLK>>>();
    k_scanB<<<1, 128>>>();
    k_scanC<<<NSB, SBLK>>>();
    k_fill <<<(NE + 255) / 256, 256>>>(src, dst);

    // layer 1
    k_agg_bf<<<(NN * 32 + 255) / 256, 256>>>((const __nv_bfloat16*)p_fb, (float*)p_agg);
    k_gemm128<<<(NN + 63) / 64, 256, SMEM_GEMM>>>((const float*)p_agg, W1, b1,
                                                  (float*)p_h1, (__nv_bfloat16*)p_h1b);

    // layer 2
    k_agg_bf<<<(NN * 32 + 255) / 256, 256>>>((const __nv_bfloat16*)p_h1b, (float*)p_agg);
    k_gemm128<<<(NN + 63) / 64, 256, SMEM_GEMM>>>((const float*)p_agg, W2, b2,
                                                  (float*)p_h2, (__nv_bfloat16*)0);

    // logits + log_softmax
    k_logits<<<(NN + 127) / 128, 256, SMEM_LOGITS>>>(Wl, bl, out);
}